// round 4
// baseline (speedup 1.0000x reference)
#include <cuda_runtime.h>
#include <cuda_bf16.h>
#include <cstdint>
#include <cmath>

#define NN 8192
#define DD 128
#define NBLK 64
#define NTRI (NBLK * (NBLK + 1) / 2)   // 2080 lower-triangle 128x128 tiles
#define TILEB 32768                    // one 128x128 bf16 tile in smem (blocked SW128)
#define SMEM_DYN (1024 + 2 * TILEB + 64)
#define TMEM_COLS 256                  // D1 (128 cols) + D2 (128 cols)
#define IDESC_F16_BF16_M128_N128 0x8200490u

// tcgen05 is arch-accelerated: legal only in the sm_103a/feature-specific pass.
// The plain compute_103 PTX pass (JIT fallback target, never executed on GB300
// where exact-match SASS is loaded) gets stubs.
#if defined(__CUDA_ARCH_FEAT_SM103_ALL) || defined(__CUDA_ARCH_FEAT_SM100_ALL) || \
    defined(__CUDA_ARCH_SPECIFIC__) || defined(__CUDA_ARCH_FAMILY_SPECIFIC__)
#define HAVE_TCGEN05 1
#endif

// Scratch (device globals: allocation is banned in kernel_launch)
__device__ __nv_bfloat16 d_X[NN * DD];
__device__ float d_partials[NTRI];

// ---------------------------------------------------------------------------
// Kernel 1: row-normalize -> bf16. 4 rows per warp (MLP=4).
// ---------------------------------------------------------------------------
__global__ void norm_kernel(const float* __restrict__ emb) {
    int w    = (blockIdx.x * blockDim.x + threadIdx.x) >> 5;
    int lane = threadIdx.x & 31;
    int row0 = w * 4;
    float4 v[4];
    #pragma unroll
    for (int i = 0; i < 4; i++)
        v[i] = reinterpret_cast<const float4*>(emb + (size_t)(row0 + i) * DD)[lane];
    #pragma unroll
    for (int i = 0; i < 4; i++) {
        float ss = v[i].x * v[i].x + v[i].y * v[i].y + v[i].z * v[i].z + v[i].w * v[i].w;
        #pragma unroll
        for (int o = 16; o > 0; o >>= 1) ss += __shfl_xor_sync(0xffffffffu, ss, o);
        float sc = 1.0f / fmaxf(sqrtf(ss), 1e-8f);
        __nv_bfloat162* dst = reinterpret_cast<__nv_bfloat162*>(d_X + (size_t)(row0 + i) * DD);
        dst[lane * 2]     = __floats2bfloat162_rn(v[i].x * sc, v[i].y * sc);
        dst[lane * 2 + 1] = __floats2bfloat162_rn(v[i].z * sc, v[i].w * sc);
    }
}

// ---------------------------------------------------------------------------
// tcgen05 helpers (guarded)
// ---------------------------------------------------------------------------
__device__ __forceinline__ uint32_t smem_u32(const void* p) {
    return (uint32_t)__cvta_generic_to_shared(p);
}
__device__ __forceinline__ uint32_t elect_one() {
    uint32_t pred;
    asm volatile("{\n\t.reg .pred p;\n\telect.sync _|p, 0xFFFFFFFF;\n\t"
                 "selp.b32 %0, 1, 0, p;\n\t}" : "=r"(pred));
    return pred;
}
// 64-bit SMEM descriptor: SW128, version=1 (Blackwell), LBO=1, SBO=64 (K-major)
__device__ __forceinline__ uint64_t make_desc(uint32_t addr) {
    const uint64_t base = (uint64_t(2) << 61) | (uint64_t(1) << 46) |
                          (uint64_t(64) << 32) | (uint64_t(1) << 16);
    return base | ((uint64_t)(addr >> 4) & 0x3FFF);
}

#ifdef HAVE_TCGEN05
#define TC_ALLOC(scal, n)                                                          \
    asm volatile("tcgen05.alloc.cta_group::1.sync.aligned.shared::cta.b32 [%0], %1;" \
                 :: "r"(scal), "r"(n) : "memory")
#define TC_RELINQ() \
    asm volatile("tcgen05.relinquish_alloc_permit.cta_group::1.sync.aligned;")
#define TC_DEALLOC(t, n)                                                \
    asm volatile("tcgen05.dealloc.cta_group::1.sync.aligned.b32 %0, %1;" \
                 :: "r"(t), "r"(n))
#define TC_COMMIT(mb)                                                                    \
    asm volatile("tcgen05.commit.cta_group::1.mbarrier::arrive::one.shared::cluster.b64 [%0];" \
                 :: "r"(mb) : "memory")
#define TC_FENCE_AFTER()  asm volatile("tcgen05.fence::after_thread_sync;" ::: "memory")
#define TC_FENCE_BEFORE() asm volatile("tcgen05.fence::before_thread_sync;" ::: "memory")
#define TC_WAIT_LD()      asm volatile("tcgen05.wait::ld.sync.aligned;" ::: "memory")
__device__ __forceinline__ void mma_f16_ss(uint32_t d, uint64_t a, uint64_t b,
                                           uint32_t idesc, uint32_t en) {
    asm volatile("{\n\t.reg .pred p;\n\tsetp.ne.u32 p, %5, 0;\n\t"
                 "tcgen05.mma.cta_group::1.kind::f16 [%0], %1, %2, %3, {%4,%4,%4,%4}, p;\n\t}"
                 :: "r"(d), "l"(a), "l"(b), "r"(idesc), "r"(0u), "r"(en) : "memory");
}
#define LDTM_X32(r, a)                                                        \
    asm volatile("tcgen05.ld.sync.aligned.32x32b.x32.b32 "                     \
        "{%0,%1,%2,%3,%4,%5,%6,%7,%8,%9,%10,%11,%12,%13,%14,%15,"              \
        "%16,%17,%18,%19,%20,%21,%22,%23,%24,%25,%26,%27,%28,%29,%30,%31}, [%32];" \
        : "=r"((r)[0]),"=r"((r)[1]),"=r"((r)[2]),"=r"((r)[3]),                 \
          "=r"((r)[4]),"=r"((r)[5]),"=r"((r)[6]),"=r"((r)[7]),                 \
          "=r"((r)[8]),"=r"((r)[9]),"=r"((r)[10]),"=r"((r)[11]),               \
          "=r"((r)[12]),"=r"((r)[13]),"=r"((r)[14]),"=r"((r)[15]),             \
          "=r"((r)[16]),"=r"((r)[17]),"=r"((r)[18]),"=r"((r)[19]),             \
          "=r"((r)[20]),"=r"((r)[21]),"=r"((r)[22]),"=r"((r)[23]),             \
          "=r"((r)[24]),"=r"((r)[25]),"=r"((r)[26]),"=r"((r)[27]),             \
          "=r"((r)[28]),"=r"((r)[29]),"=r"((r)[30]),"=r"((r)[31])              \
        : "r"(a))
#else
// Stubs for the baseline-PTX pass (not executed on GB300; SASS path is exact-match)
#define TC_ALLOC(scal, n)  do { } while (0)
#define TC_RELINQ()        do { } while (0)
#define TC_DEALLOC(t, n)   do { (void)(t); } while (0)
#define TC_COMMIT(mb)                                                     \
    asm volatile("mbarrier.arrive.shared.b64 _, [%0];" :: "r"(mb) : "memory")
#define TC_FENCE_AFTER()   do { } while (0)
#define TC_FENCE_BEFORE()  do { } while (0)
#define TC_WAIT_LD()       do { } while (0)
__device__ __forceinline__ void mma_f16_ss(uint32_t, uint64_t, uint64_t,
                                           uint32_t, uint32_t) {}
#define LDTM_X32(r, a)                                           \
    do { _Pragma("unroll") for (int _i = 0; _i < 32; _i++) (r)[_i] = 0u; (void)(a); } while (0)
#endif

// Blocked-atom SW128 byte offset inside a 128row x 256B tile.
// kc = 16B chunk index within the row (0..15). atom_col = kc/8, 16 atom-rows per col.
__device__ __forceinline__ uint32_t tile_off(int row, int kc) {
    uint32_t off = (uint32_t)(((row >> 3) + ((kc >> 3) << 4)) * 1024 +
                              (row & 7) * 128 + (kc & 7) * 16);
    return off ^ ((off >> 3) & 0x70);
}

// ---------------------------------------------------------------------------
// Kernel 2: per lower-triangle tile: D1 = A·B^T and (off-diag) D2 = B·A^T via
// tcgen05, then fused MSE epilogues against S[ti,tj] and S[tj,ti].
// ---------------------------------------------------------------------------
__global__ void __launch_bounds__(256, 2)
mse_gemm_tc(const float* __restrict__ S) {
    extern __shared__ char dsm[];
    __shared__ float wsum[8];

    const int tid  = threadIdx.x;
    const int wid  = tid >> 5;
    const int lane = tid & 31;

    const uint32_t sbase     = smem_u32(dsm);
    const uint32_t tile_base = (sbase + 1023u) & ~1023u;
    const uint32_t smA  = tile_base;
    const uint32_t smB  = tile_base + TILEB;
    const uint32_t scal = smB + TILEB;       // [scal]: tmem ptr, [scal+8]: mbarrier
    const uint32_t mbar = scal + 8;
    char* pA = dsm + (smA - sbase);
    char* pB = dsm + (smB - sbase);

    // Triangular decode: b = trow*(trow+1)/2 + tcol, tcol <= trow.
    const int b = blockIdx.x;
    int trow = (int)((sqrt((double)(8.0 * b + 1.0)) - 1.0) * 0.5);
    while ((trow + 1) * (trow + 2) / 2 <= b) trow++;
    while (trow * (trow + 1) / 2 > b) trow--;
    const int ti = b - trow * (trow + 1) / 2;   // tile row (ti <= tj)
    const int tj = trow;                        // tile col
    const bool offdiag = (ti != tj);

    // TMEM alloc (warp 0) + mbarrier init (thread 0)
    if (wid == 0) TC_ALLOC(scal, TMEM_COLS);
    if (tid == 0)
        asm volatile("mbarrier.init.shared.b64 [%0], 1;" :: "r"(mbar) : "memory");

    // Fill A and B tiles (bf16, blocked-atom SW128). 8 iters x 2 tiles per thread.
    const int rowA0 = ti * 128, rowB0 = tj * 128;
    #pragma unroll
    for (int i = 0; i < 8; i++) {
        int idx = tid + i * 256;
        int r   = idx >> 4;        // 0..127
        int kc  = idx & 15;        // 16B chunk
        uint32_t off = tile_off(r, kc);
        *reinterpret_cast<uint4*>(pA + off) =
            *reinterpret_cast<const uint4*>(d_X + (size_t)(rowA0 + r) * DD + kc * 8);
        *reinterpret_cast<uint4*>(pB + off) =
            *reinterpret_cast<const uint4*>(d_X + (size_t)(rowB0 + r) * DD + kc * 8);
    }
    asm volatile("fence.proxy.async.shared::cta;" ::: "memory");
    __syncthreads();

    uint32_t tmem_base;
    asm volatile("ld.shared.b32 %0, [%1];" : "=r"(tmem_base) : "r"(scal));

    // MMA issue (one elected thread). 8 k-steps of 16 bf16; desc offset crosses
    // the atom-col boundary at k=64: 16 atoms * 1024B = 1024 16B-units.
    if (wid == 0 && elect_one()) {
        const uint64_t da = make_desc(smA);
        const uint64_t db = make_desc(smB);
        const uint32_t offs[8] = {0, 2, 4, 6, 1024, 1026, 1028, 1030};
        #pragma unroll
        for (int k = 0; k < 8; k++)
            mma_f16_ss(tmem_base, da + offs[k], db + offs[k],
                       IDESC_F16_BF16_M128_N128, k > 0);
        if (offdiag) {
            #pragma unroll
            for (int k = 0; k < 8; k++)
                mma_f16_ss(tmem_base + 128, db + offs[k], da + offs[k],
                           IDESC_F16_BF16_M128_N128, k > 0);
        }
        TC_COMMIT(mbar);
    }

    // Wait for MMA completion (all threads).
    {
        uint32_t done;
        asm volatile("{\n\t.reg .pred p;\n\t"
                     "mbarrier.try_wait.parity.acquire.cta.shared::cta.b64 p, [%1], 0;\n\t"
                     "selp.b32 %0, 1, 0, p;\n\t}" : "=r"(done) : "r"(mbar) : "memory");
        if (!done) {
            asm volatile("{\n\t.reg .pred P1;\n\t"
                         "W0_%=:\n\t"
                         "mbarrier.try_wait.parity.acquire.cta.shared::cta.b64 P1, [%0], 0, 0x989680;\n\t"
                         "@P1 bra.uni WD_%=;\n\t"
                         "bra.uni W0_%=;\n\t"
                         "WD_%=:\n\t}" :: "r"(mbar) : "memory");
        }
    }
    TC_FENCE_AFTER();

    // Epilogue: 8 warps; warp covers TMEM subpartition sub=(wid&3) (rows sub*32+lane)
    // and column chunks {0,1} (warps 0-3) or {2,3} (warps 4-7). All S reads are
    // row-coalesced float4 (the mirror tile uses D2 = C^T, no transposed access).
    const int sub  = wid & 3;
    const int half = wid >> 2;
    const uint32_t tm_warp = ((uint32_t)sub) << 21;
    float local = 0.f;
    {
        const int rowS = ti * 128 + sub * 32 + lane;
        const float4* srow = reinterpret_cast<const float4*>(S + (size_t)rowS * NN + tj * 128);
        #pragma unroll
        for (int c = 0; c < 2; c++) {
            const int cc = half * 2 + c;
            uint32_t r[32];
            LDTM_X32(r, tmem_base + cc * 32 + tm_warp);
            TC_WAIT_LD();
            float l0 = 0.f, l1 = 0.f, l2 = 0.f, l3 = 0.f;
            #pragma unroll
            for (int q = 0; q < 8; q++) {
                float4 s4 = srow[cc * 8 + q];
                float e0 = __uint_as_float(r[q * 4 + 0]) - s4.x;
                float e1 = __uint_as_float(r[q * 4 + 1]) - s4.y;
                float e2 = __uint_as_float(r[q * 4 + 2]) - s4.z;
                float e3 = __uint_as_float(r[q * 4 + 3]) - s4.w;
                l0 += e0 * e0; l1 += e1 * e1; l2 += e2 * e2; l3 += e3 * e3;
            }
            local += (l0 + l1) + (l2 + l3);
        }
    }
    if (offdiag) {
        const int rowS = tj * 128 + sub * 32 + lane;
        const float4* srow = reinterpret_cast<const float4*>(S + (size_t)rowS * NN + ti * 128);
        #pragma unroll
        for (int c = 0; c < 2; c++) {
            const int cc = half * 2 + c;
            uint32_t r[32];
            LDTM_X32(r, tmem_base + 128 + cc * 32 + tm_warp);
            TC_WAIT_LD();
            float l0 = 0.f, l1 = 0.f, l2 = 0.f, l3 = 0.f;
            #pragma unroll
            for (int q = 0; q < 8; q++) {
                float4 s4 = srow[cc * 8 + q];
                float e0 = __uint_as_float(r[q * 4 + 0]) - s4.x;
                float e1 = __uint_as_float(r[q * 4 + 1]) - s4.y;
                float e2 = __uint_as_float(r[q * 4 + 2]) - s4.z;
                float e3 = __uint_as_float(r[q * 4 + 3]) - s4.w;
                l0 += e0 * e0; l1 += e1 * e1; l2 += e2 * e2; l3 += e3 * e3;
            }
            local += (l0 + l1) + (l2 + l3);
        }
    }
    TC_FENCE_BEFORE();

    // Reduce 256 threads -> 1 partial
    #pragma unroll
    for (int o = 16; o > 0; o >>= 1) local += __shfl_xor_sync(0xffffffffu, local, o);
    if (lane == 0) wsum[wid] = local;
    __syncthreads();

    // Cleanup: mbarrier invalidate (graph replays re-init it) + TMEM release.
    if (tid == 0)
        asm volatile("mbarrier.inval.shared.b64 [%0];" :: "r"(mbar) : "memory");
    if (wid == 0) {
        TC_RELINQ();
        TC_DEALLOC(tmem_base, TMEM_COLS);
        float v = (lane < 8) ? wsum[lane] : 0.f;
        #pragma unroll
        for (int o = 4; o > 0; o >>= 1) v += __shfl_xor_sync(0xffffffffu, v, o);
        if (lane == 0) d_partials[b] = v;
    }
}

// ---------------------------------------------------------------------------
// Kernel 3: deterministic fixed-order reduction of 2080 partials -> loss.
// ---------------------------------------------------------------------------
__global__ void finalize_kernel(float* __restrict__ out) {
    __shared__ float red[256];
    float s = 0.f;
    for (int i = threadIdx.x; i < NTRI; i += 256) s += d_partials[i];
    red[threadIdx.x] = s;
    __syncthreads();
    #pragma unroll
    for (int o = 128; o > 0; o >>= 1) {
        if (threadIdx.x < o) red[threadIdx.x] += red[threadIdx.x + o];
        __syncthreads();
    }
    if (threadIdx.x == 0) out[0] = red[0] / ((float)NN * (float)NN);
}

// ---------------------------------------------------------------------------
extern "C" void kernel_launch(void* const* d_in, const int* in_sizes, int n_in,
                              void* d_out, int out_size) {
    const float* emb = (const float*)d_in[0];   // [8192, 128] fp32
    const float* S   = (const float*)d_in[1];   // [8192, 8192] fp32

    cudaFuncSetAttribute(mse_gemm_tc, cudaFuncAttributeMaxDynamicSharedMemorySize, SMEM_DYN);
    norm_kernel<<<256, 256>>>(emb);             // 4 rows per warp
    mse_gemm_tc<<<NTRI, 256, SMEM_DYN>>>(S);
    finalize_kernel<<<1, 256>>>((float*)d_out);
}

// round 9
// speedup vs baseline: 1.1387x; 1.1387x over previous
#include <cuda_runtime.h>
#include <cuda_bf16.h>
#include <cstdint>
#include <cmath>

#define NN 8192
#define DD 128
#define NBLK 64
#define NTRI (NBLK * (NBLK + 1) / 2)   // 2080 lower-triangle 128x128 tiles
#define NCTA 148
#define NTHR 512
#define TILEB 32768                    // one 128x128 bf16 tile (blocked SW128)
#define STAGEB (2 * TILEB)             // A+B per stage
#define SMEM_DYN (1024 + 2 * STAGEB + 64)
#define TMEM_COLS 512                  // 2 stages x (D1:128 + D2:128)
#define IDESC_F16_BF16_M128_N128 0x8200490u

// tcgen05 is arch-accelerated: legal only in the arch-specific pass. The plain
// compute_103 PTX pass (JIT fallback, never executed on GB300) gets stubs.
#if defined(__CUDA_ARCH_FEAT_SM103_ALL) || defined(__CUDA_ARCH_FEAT_SM100_ALL) || \
    defined(__CUDA_ARCH_SPECIFIC__) || defined(__CUDA_ARCH_FAMILY_SPECIFIC__)
#define HAVE_TCGEN05 1
#endif

__device__ __nv_bfloat16 d_X[NN * DD];
__device__ float d_partials[NCTA];

// ---------------------------------------------------------------------------
// Kernel 1: row-normalize -> bf16. One warp per row.
// ---------------------------------------------------------------------------
__global__ void norm_kernel(const float* __restrict__ emb) {
    int w    = (blockIdx.x * blockDim.x + threadIdx.x) >> 5;
    int lane = threadIdx.x & 31;
    const float4 v = reinterpret_cast<const float4*>(emb + (size_t)w * DD)[lane];
    float ss = v.x * v.x + v.y * v.y + v.z * v.z + v.w * v.w;
    #pragma unroll
    for (int o = 16; o > 0; o >>= 1) ss += __shfl_xor_sync(0xffffffffu, ss, o);
    float sc = 1.0f / fmaxf(sqrtf(ss), 1e-8f);
    __nv_bfloat162* dst = reinterpret_cast<__nv_bfloat162*>(d_X + (size_t)w * DD);
    dst[lane * 2]     = __floats2bfloat162_rn(v.x * sc, v.y * sc);
    dst[lane * 2 + 1] = __floats2bfloat162_rn(v.z * sc, v.w * sc);
}

// ---------------------------------------------------------------------------
// tcgen05 helpers (guarded)
// ---------------------------------------------------------------------------
__device__ __forceinline__ uint32_t smem_u32(const void* p) {
    return (uint32_t)__cvta_generic_to_shared(p);
}
__device__ __forceinline__ uint32_t elect_one() {
    uint32_t pred;
    asm volatile("{\n\t.reg .pred p;\n\telect.sync _|p, 0xFFFFFFFF;\n\t"
                 "selp.b32 %0, 1, 0, p;\n\t}" : "=r"(pred));
    return pred;
}
__device__ __forceinline__ uint64_t make_desc(uint32_t addr) {
    const uint64_t base = (uint64_t(2) << 61) | (uint64_t(1) << 46) |
                          (uint64_t(64) << 32) | (uint64_t(1) << 16);
    return base | ((uint64_t)(addr >> 4) & 0x3FFF);
}

#ifdef HAVE_TCGEN05
#define TC_ALLOC(scal, n)                                                          \
    asm volatile("tcgen05.alloc.cta_group::1.sync.aligned.shared::cta.b32 [%0], %1;" \
                 :: "r"(scal), "r"(n) : "memory")
#define TC_RELINQ() \
    asm volatile("tcgen05.relinquish_alloc_permit.cta_group::1.sync.aligned;")
#define TC_DEALLOC(t, n)                                                \
    asm volatile("tcgen05.dealloc.cta_group::1.sync.aligned.b32 %0, %1;" \
                 :: "r"(t), "r"(n))
#define TC_COMMIT(mb)                                                                    \
    asm volatile("tcgen05.commit.cta_group::1.mbarrier::arrive::one.shared::cluster.b64 [%0];" \
                 :: "r"(mb) : "memory")
#define TC_FENCE_AFTER()  asm volatile("tcgen05.fence::after_thread_sync;" ::: "memory")
#define TC_FENCE_BEFORE() asm volatile("tcgen05.fence::before_thread_sync;" ::: "memory")
#define TC_WAIT_LD()      asm volatile("tcgen05.wait::ld.sync.aligned;" ::: "memory")
__device__ __forceinline__ void mma_f16_ss(uint32_t d, uint64_t a, uint64_t b,
                                           uint32_t idesc, uint32_t en) {
    asm volatile("{\n\t.reg .pred p;\n\tsetp.ne.u32 p, %5, 0;\n\t"
                 "tcgen05.mma.cta_group::1.kind::f16 [%0], %1, %2, %3, {%4,%4,%4,%4}, p;\n\t}"
                 :: "r"(d), "l"(a), "l"(b), "r"(idesc), "r"(0u), "r"(en) : "memory");
}
#define LDTM_X32(r, a)                                                        \
    asm volatile("tcgen05.ld.sync.aligned.32x32b.x32.b32 "                     \
        "{%0,%1,%2,%3,%4,%5,%6,%7,%8,%9,%10,%11,%12,%13,%14,%15,"              \
        "%16,%17,%18,%19,%20,%21,%22,%23,%24,%25,%26,%27,%28,%29,%30,%31}, [%32];" \
        : "=r"((r)[0]),"=r"((r)[1]),"=r"((r)[2]),"=r"((r)[3]),                 \
          "=r"((r)[4]),"=r"((r)[5]),"=r"((r)[6]),"=r"((r)[7]),                 \
          "=r"((r)[8]),"=r"((r)[9]),"=r"((r)[10]),"=r"((r)[11]),               \
          "=r"((r)[12]),"=r"((r)[13]),"=r"((r)[14]),"=r"((r)[15]),             \
          "=r"((r)[16]),"=r"((r)[17]),"=r"((r)[18]),"=r"((r)[19]),             \
          "=r"((r)[20]),"=r"((r)[21]),"=r"((r)[22]),"=r"((r)[23]),             \
          "=r"((r)[24]),"=r"((r)[25]),"=r"((r)[26]),"=r"((r)[27]),             \
          "=r"((r)[28]),"=r"((r)[29]),"=r"((r)[30]),"=r"((r)[31])              \
        : "r"(a))
#else
#define TC_ALLOC(scal, n)  do { } while (0)
#define TC_RELINQ()        do { } while (0)
#define TC_DEALLOC(t, n)   do { (void)(t); } while (0)
#define TC_COMMIT(mb)                                                     \
    asm volatile("mbarrier.arrive.shared.b64 _, [%0];" :: "r"(mb) : "memory")
#define TC_FENCE_AFTER()   do { } while (0)
#define TC_FENCE_BEFORE()  do { } while (0)
#define TC_WAIT_LD()       do { } while (0)
__device__ __forceinline__ void mma_f16_ss(uint32_t, uint64_t, uint64_t,
                                           uint32_t, uint32_t) {}
#define LDTM_X32(r, a)                                           \
    do { _Pragma("unroll") for (int _i = 0; _i < 32; _i++) (r)[_i] = 0u; (void)(a); } while (0)
#endif

// Blocked-atom SW128 byte offset inside a 128row x 256B tile.
__device__ __forceinline__ uint32_t tile_off(int row, int kc) {
    uint32_t off = (uint32_t)(((row >> 3) + ((kc >> 3) << 4)) * 1024 +
                              (row & 7) * 128 + (kc & 7) * 16);
    return off ^ ((off >> 3) & 0x70);
}

__device__ __forceinline__ void tri_decode(int t, int& ti, int& tj) {
    int trow = (int)((sqrt((double)(8.0 * t + 1.0)) - 1.0) * 0.5);
    while ((trow + 1) * (trow + 2) / 2 <= t) trow++;
    while (trow * (trow + 1) / 2 > t) trow--;
    ti = t - trow * (trow + 1) / 2;   // ti <= tj
    tj = trow;
}

__device__ __forceinline__ void mbar_wait(uint32_t mb, uint32_t parity) {
    uint32_t done;
    asm volatile("{\n\t.reg .pred p;\n\t"
                 "mbarrier.try_wait.parity.acquire.cta.shared::cta.b64 p, [%1], %2;\n\t"
                 "selp.b32 %0, 1, 0, p;\n\t}" : "=r"(done) : "r"(mb), "r"(parity) : "memory");
    if (!done) {
        asm volatile("{\n\t.reg .pred P1;\n\t"
                     "W0_%=:\n\t"
                     "mbarrier.try_wait.parity.acquire.cta.shared::cta.b64 P1, [%0], %1, 0x989680;\n\t"
                     "@P1 bra.uni WD_%=;\n\t"
                     "bra.uni W0_%=;\n\t"
                     "WD_%=:\n\t}" :: "r"(mb), "r"(parity) : "memory");
    }
}

// ---------------------------------------------------------------------------
// Kernel 2: persistent CTAs, double-buffered (smem stage, TMEM half) pipeline.
// Tile k+1's MMA runs while tile k's epilogue streams S.
// ---------------------------------------------------------------------------
__global__ void __launch_bounds__(NTHR, 1)
mse_gemm_tc(const float* __restrict__ S) {
    extern __shared__ char dsm[];
    __shared__ float wsum[16];

    const int tid  = threadIdx.x;
    const int wid  = tid >> 5;
    const int lane = tid & 31;

    const uint32_t sbase     = smem_u32(dsm);
    const uint32_t tile_base = (sbase + 1023u) & ~1023u;
    const uint32_t ctrl = tile_base + 2 * STAGEB;  // [ctrl]: tmem ptr, +8/+16: mbarriers
    const uint32_t mb0  = ctrl + 8;
    char* const pbase = dsm + (tile_base - sbase);

    // One-time setup
    if (wid == 0) TC_ALLOC(ctrl, TMEM_COLS);
    if (tid == 0) {
        asm volatile("mbarrier.init.shared.b64 [%0], 1;" :: "r"(mb0)     : "memory");
        asm volatile("mbarrier.init.shared.b64 [%0], 1;" :: "r"(mb0 + 8) : "memory");
    }
    __syncthreads();
    uint32_t tmem_base;
    asm volatile("ld.shared.b32 %0, [%1];" : "=r"(tmem_base) : "r"(ctrl));

    const int K = (NTRI - blockIdx.x + NCTA - 1) / NCTA;   // tiles for this CTA
    int ph[2] = {0, 0};

    // --- helpers -----------------------------------------------------------
    auto fill = [&](int p, int ti, int tj) {
        char* pA = pbase + p * STAGEB;
        char* pB = pA + TILEB;
        const int rA = ti * 128, rB = tj * 128;
        #pragma unroll
        for (int i = 0; i < 4; i++) {
            int idx = tid + i * NTHR;          // 0..2047
            int r   = idx >> 4;
            int kc  = idx & 15;
            uint32_t off = tile_off(r, kc);
            *reinterpret_cast<uint4*>(pA + off) =
                *reinterpret_cast<const uint4*>(d_X + (size_t)(rA + r) * DD + kc * 8);
            *reinterpret_cast<uint4*>(pB + off) =
                *reinterpret_cast<const uint4*>(d_X + (size_t)(rB + r) * DD + kc * 8);
        }
        asm volatile("fence.proxy.async.shared::cta;" ::: "memory");
    };
    auto issue = [&](int p, bool offdiag) {                 // elected thread only
        const uint64_t da = make_desc(tile_base + p * STAGEB);
        const uint64_t db = make_desc(tile_base + p * STAGEB + TILEB);
        const uint32_t d1 = tmem_base + p * 256;
        const uint32_t offs[8] = {0, 2, 4, 6, 1024, 1026, 1028, 1030};
        #pragma unroll
        for (int k = 0; k < 8; k++)
            mma_f16_ss(d1, da + offs[k], db + offs[k], IDESC_F16_BF16_M128_N128, k > 0);
        if (offdiag) {
            #pragma unroll
            for (int k = 0; k < 8; k++)
                mma_f16_ss(d1 + 128, db + offs[k], da + offs[k],
                           IDESC_F16_BF16_M128_N128, k > 0);
        }
        TC_COMMIT(mb0 + 8 * p);
    };

    // Epilogue warp mapping: 16 warps; sub = wid&3 (the warp's own SMSP /
    // TMEM subpartition), chunk = wid>>2 (32-col slice). S reads are
    // row-coalesced float4.
    const int sub   = wid & 3;
    const int chunk = wid >> 2;
    const uint32_t tm_sub = ((uint32_t)sub) << 21;
    float local = 0.f;
    auto epilogue_half = [&](uint32_t tmaddr, int rowS_base, int colS_base) {
        const int rowS = rowS_base + sub * 32 + lane;
        const float4* srow =
            reinterpret_cast<const float4*>(S + (size_t)rowS * NN + colS_base) + chunk * 8;
        uint32_t r[32];
        LDTM_X32(r, tmaddr + chunk * 32 + tm_sub);
        TC_WAIT_LD();
        float l0 = 0.f, l1 = 0.f, l2 = 0.f, l3 = 0.f;
        #pragma unroll
        for (int q = 0; q < 8; q++) {
            float4 s4 = srow[q];
            float e0 = __uint_as_float(r[q * 4 + 0]) - s4.x;
            float e1 = __uint_as_float(r[q * 4 + 1]) - s4.y;
            float e2 = __uint_as_float(r[q * 4 + 2]) - s4.z;
            float e3 = __uint_as_float(r[q * 4 + 3]) - s4.w;
            l0 += e0 * e0; l1 += e1 * e1; l2 += e2 * e2; l3 += e3 * e3;
        }
        local += (l0 + l1) + (l2 + l3);
    };
    // -----------------------------------------------------------------------

    // Prologue: stage 0 <- tile 0
    int ti0, tj0;
    tri_decode(blockIdx.x, ti0, tj0);
    fill(0, ti0, tj0);
    __syncthreads();
    if (wid == 0 && elect_one()) issue(0, ti0 != tj0);

    int ti_c = ti0, tj_c = tj0;
    for (int k = 0; k < K; k++) {
        const int p = k & 1;
        int ti_n = 0, tj_n = 0;
        const bool have_next = (k + 1 < K);
        if (have_next) {
            tri_decode(blockIdx.x + (k + 1) * NCTA, ti_n, tj_n);
            fill(p ^ 1, ti_n, tj_n);                   // overlaps MMA k in flight
        }
        __syncthreads();                               // fill visible; epilogue k-1 done
        if (have_next && wid == 0 && elect_one()) issue(p ^ 1, ti_n != tj_n);

        mbar_wait(mb0 + 8 * p, ph[p]);                 // MMA k complete
        ph[p] ^= 1;
        TC_FENCE_AFTER();

        const uint32_t d1 = tmem_base + p * 256;
        epilogue_half(d1, ti_c * 128, tj_c * 128);     // C vs S[ti,tj]
        if (ti_c != tj_c)
            epilogue_half(d1 + 128, tj_c * 128, ti_c * 128);  // C^T vs S[tj,ti]
        TC_FENCE_BEFORE();

        ti_c = ti_n; tj_c = tj_n;
    }

    // Reduce 512 threads -> 1 partial (fixed order, deterministic)
    #pragma unroll
    for (int o = 16; o > 0; o >>= 1) local += __shfl_xor_sync(0xffffffffu, local, o);
    if (lane == 0) wsum[wid] = local;
    __syncthreads();
    if (tid == 0) {
        asm volatile("mbarrier.inval.shared.b64 [%0];" :: "r"(mb0)     : "memory");
        asm volatile("mbarrier.inval.shared.b64 [%0];" :: "r"(mb0 + 8) : "memory");
    }
    if (wid == 0) {
        TC_RELINQ();
        TC_DEALLOC(tmem_base, TMEM_COLS);
        float v = (lane < 16) ? wsum[lane] : 0.f;
        #pragma unroll
        for (int o = 8; o > 0; o >>= 1) v += __shfl_xor_sync(0xffffffffu, v, o);
        if (lane == 0) d_partials[blockIdx.x] = v;
    }
}

// ---------------------------------------------------------------------------
// Kernel 3: deterministic fixed-order reduction of 148 partials -> loss.
// ---------------------------------------------------------------------------
__global__ void finalize_kernel(float* __restrict__ out) {
    __shared__ float red[256];
    float s = 0.f;
    for (int i = threadIdx.x; i < NCTA; i += 256) s += d_partials[i];
    red[threadIdx.x] = s;
    __syncthreads();
    #pragma unroll
    for (int o = 128; o > 0; o >>= 1) {
        if (threadIdx.x < o) red[threadIdx.x] += red[threadIdx.x + o];
        __syncthreads();
    }
    if (threadIdx.x == 0) out[0] = red[0] / ((float)NN * (float)NN);
}

// ---------------------------------------------------------------------------
extern "C" void kernel_launch(void* const* d_in, const int* in_sizes, int n_in,
                              void* d_out, int out_size) {
    const float* emb = (const float*)d_in[0];   // [8192, 128] fp32
    const float* S   = (const float*)d_in[1];   // [8192, 8192] fp32

    cudaFuncSetAttribute(mse_gemm_tc, cudaFuncAttributeMaxDynamicSharedMemorySize, SMEM_DYN);
    norm_kernel<<<NN / 8, 256>>>(emb);          // one warp per row
    mse_gemm_tc<<<NCTA, NTHR, SMEM_DYN>>>(S);
    finalize_kernel<<<1, 256>>>((float*)d_out);
}